// round 14
// baseline (speedup 1.0000x reference)
#include <cuda_runtime.h>
#include <cuda_fp16.h>
#include <math.h>
#include <stdint.h>

// Problem dims (fixed)
#define BB 2
#define SS 4096
#define DD 512

// Scratch (device globals: allocation-free rule)
__device__ __align__(256) __half g_qh[(size_t)BB * SS * DD];   // Q [b][s][d] fp16
__device__ __align__(256) __half g_kh[(size_t)BB * SS * DD];   // K [b][s][d] fp16
__device__ __align__(256) __half g_vt[(size_t)BB * DD * SS];   // V^T [b][d][s] fp16
__device__ __align__(256) __half g_p [(size_t)BB * SS * SS];   // unnormalized exp(S) fp16
__device__ __align__(256) float  g_part[(size_t)BB * SS * 64]; // partial row sums
__device__ __align__(256) float  g_rsum[(size_t)BB * SS];      // 1 / rowsum

__device__ __forceinline__ uint32_t pack2(float lo, float hi) {
    __half2 h = __floats2half2_rn(lo, hi);
    return *(uint32_t*)&h;
}
__device__ __forceinline__ uint32_t smem_u32(const void* p) {
    uint32_t a;
    asm("{ .reg .u64 t; cvta.to.shared.u64 t, %1; cvt.u32.u64 %0, t; }"
        : "=r"(a) : "l"(p));
    return a;
}

#define CPA16(dst, src) \
    asm volatile("cp.async.cg.shared.global [%0], [%1], 16;" \
                 :: "r"(dst), "l"(src) : "memory")
#define CPA_COMMIT() asm volatile("cp.async.commit_group;" ::: "memory")
#define CPA_WAIT2()  asm volatile("cp.async.wait_group 2;" ::: "memory")

// ===========================================================================
// NT fp16-operand GEMM, 4-stage cp.async pipeline.
// MODE 0 (QK): epilogue e = expf(scale*acc) -> fp16 P + partial row sums.
// MODE 1 (PV): epilogue C = acc * rsum_inv[row] (fp32).
// CTA 128x128x32(halves), 128 threads = 4 warps (2x2), warp tile 64x64.
// __launch_bounds__(128,3): cap regs ~170 for 3 CTAs/SM (12 warps) —
// B-fragments loaded per-nt (2 live regs) to fit.
// ===========================================================================
template <int MODE>
__global__ void __launch_bounds__(128, 3)
gemm_h_nt(const __half* __restrict__ A, const __half* __restrict__ B,
          float* __restrict__ Cf, __half* __restrict__ Ch,
          float* __restrict__ part, const float* __restrict__ rsum,
          int K, int lda, int ldb, int ldc,
          long long sA, long long sB, long long sC, float alpha)
{
    extern __shared__ uint32_t sm[];            // 4 stages * 4096 words
    const uint32_t smb = smem_u32(sm);

    A += (long long)blockIdx.z * sA;
    B += (long long)blockIdx.z * sB;

    const int tid  = threadIdx.x;
    const int lane = tid & 31;
    const int wid  = tid >> 5;
    const int warp_m = wid >> 1;
    const int warp_n = wid & 1;
    const int g   = lane >> 2;
    const int tig = lane & 3;

    const int row0 = blockIdx.y * 128;
    const int col0 = blockIdx.x * 128;
    const long long zrow = (long long)blockIdx.z * SS;

    uint32_t stA[4], stB[4];
    const char* pA[4];
    const char* pB[4];
#pragma unroll
    for (int i = 0; i < 4; i++) {
        int idx = tid + i * 128;
        int r = idx >> 2, c = idx & 3;
        uint32_t off = (uint32_t)(r * 16 + ((c ^ ((r >> 1) & 3)) << 2)) * 4u;
        stA[i] = smb + off;
        stB[i] = smb + 8192 + off;
        pA[i] = (const char*)(A + (long long)(row0 + r) * lda + c * 8);
        pB[i] = (const char*)(B + (long long)(col0 + r) * ldb + c * 8);
    }

    const int lc = (g >> 1) & 3;
    int fa[4], fb[4];
#pragma unroll
    for (int c = 0; c < 4; c++) {
        fa[c] = (warp_m * 64 + g) * 16 + ((c ^ lc) << 2) + tig;
        fb[c] = 2048 + (warp_n * 64 + g) * 16 + ((c ^ lc) << 2) + tig;
    }

    float acc[4][8][4];
#pragma unroll
    for (int mt = 0; mt < 4; mt++)
#pragma unroll
        for (int nt = 0; nt < 8; nt++)
#pragma unroll
            for (int i = 0; i < 4; i++) acc[mt][nt][i] = 0.0f;

    auto FILL = [&](int t, int st) {
        const long long kb = (long long)t * 64;
        const uint32_t so = (uint32_t)st * 16384u;
#pragma unroll
        for (int i = 0; i < 4; i++) CPA16(stA[i] + so, pA[i] + kb);
#pragma unroll
        for (int i = 0; i < 4; i++) CPA16(stB[i] + so, pB[i] + kb);
    };

    auto COMPUTE = [&](int st) {
        const uint32_t* Sb = sm + st * 4096;
#pragma unroll
        for (int s = 0; s < 2; s++) {
            uint32_t af[4][4];
#pragma unroll
            for (int mt = 0; mt < 4; mt++) {
                af[mt][0] = Sb[fa[2*s]     + mt * 256];
                af[mt][1] = Sb[fa[2*s]     + mt * 256 + 128];
                af[mt][2] = Sb[fa[2*s + 1] + mt * 256];
                af[mt][3] = Sb[fa[2*s + 1] + mt * 256 + 128];
            }
#pragma unroll
            for (int nt = 0; nt < 8; nt++) {
                uint32_t b0 = Sb[fb[2*s]     + nt * 128];
                uint32_t b1 = Sb[fb[2*s + 1] + nt * 128];
#pragma unroll
                for (int mt = 0; mt < 4; mt++) {
                    asm volatile(
                        "mma.sync.aligned.m16n8k16.row.col.f32.f16.f16.f32 "
                        "{%0,%1,%2,%3}, {%4,%5,%6,%7}, {%8,%9}, {%0,%1,%2,%3};"
                        : "+f"(acc[mt][nt][0]), "+f"(acc[mt][nt][1]),
                          "+f"(acc[mt][nt][2]), "+f"(acc[mt][nt][3])
                        : "r"(af[mt][0]), "r"(af[mt][1]),
                          "r"(af[mt][2]), "r"(af[mt][3]),
                          "r"(b0), "r"(b1));
                }
            }
        }
    };

    const int nT = K / 32;                // divisible by 4 for our shapes
    FILL(0, 0); CPA_COMMIT();
    FILL(1, 1); CPA_COMMIT();
    FILL(2, 2); CPA_COMMIT();

    for (int t0 = 0; t0 < nT; t0 += 4) {
#pragma unroll
        for (int u = 0; u < 4; u++) {
            const int t = t0 + u;
            CPA_WAIT2();
            __syncthreads();
            if (t + 3 < nT) FILL(t + 3, (u + 3) & 3);
            CPA_COMMIT();
            COMPUTE(u);
        }
    }

    if (MODE == 0) {
        // exp epilogue: P (fp16, unnormalized) + deterministic partial sums
        Ch += zrow * SS;
#pragma unroll
        for (int mt = 0; mt < 4; mt++) {
            const int r = row0 + warp_m * 64 + mt * 16 + g;
            float s0 = 0.0f, s1 = 0.0f;
#pragma unroll
            for (int nt = 0; nt < 8; nt++) {
                const int c = col0 + warp_n * 64 + nt * 8 + tig * 2;
                float e0 = __expf(acc[mt][nt][0] * alpha);
                float e1 = __expf(acc[mt][nt][1] * alpha);
                float e2 = __expf(acc[mt][nt][2] * alpha);
                float e3 = __expf(acc[mt][nt][3] * alpha);
                s0 += e0 + e1;
                s1 += e2 + e3;
                *(__half2*)&Ch[(long long)r * ldc + c]       = __floats2half2_rn(e0, e1);
                *(__half2*)&Ch[(long long)(r + 8) * ldc + c] = __floats2half2_rn(e2, e3);
            }
            s0 += __shfl_xor_sync(0xFFFFFFFF, s0, 1);
            s0 += __shfl_xor_sync(0xFFFFFFFF, s0, 2);
            s1 += __shfl_xor_sync(0xFFFFFFFF, s1, 1);
            s1 += __shfl_xor_sync(0xFFFFFFFF, s1, 2);
            if (tig == 0) {
                const int slot = blockIdx.x * 2 + warp_n;
                part[(zrow + r)     * 64 + slot] = s0;
                part[(zrow + r + 8) * 64 + slot] = s1;
            }
        }
    } else {
        Cf += zrow * DD;
#pragma unroll
        for (int mt = 0; mt < 4; mt++) {
            const int r = row0 + warp_m * 64 + mt * 16 + g;
            const float inv0 = rsum[zrow + r];
            const float inv1 = rsum[zrow + r + 8];
#pragma unroll
            for (int nt = 0; nt < 8; nt++) {
                const int c = col0 + warp_n * 64 + nt * 8 + tig * 2;
                float2 v0, v1;
                v0.x = acc[mt][nt][0] * inv0; v0.y = acc[mt][nt][1] * inv0;
                v1.x = acc[mt][nt][2] * inv1; v1.y = acc[mt][nt][3] * inv1;
                *(float2*)&Cf[(long long)r * ldc + c]       = v0;
                *(float2*)&Cf[(long long)(r + 8) * ldc + c] = v1;
            }
        }
    }
}

// ---------------------------------------------------------------------------
// rowsum reduce: rsum_inv[row] = 1 / sum(part[row][0..63]).
// ---------------------------------------------------------------------------
__global__ void __launch_bounds__(256)
rowsum_inv(const float* __restrict__ part, float* __restrict__ rsum)
{
    const int row  = blockIdx.x * 8 + (threadIdx.x >> 5);
    const int lane = threadIdx.x & 31;
    const float* p = part + (long long)row * 64;
    float v = p[lane] + p[lane + 32];
#pragma unroll
    for (int o = 16; o > 0; o >>= 1)
        v += __shfl_xor_sync(0xFFFFFFFF, v, o);
    if (lane == 0) rsum[row] = 1.0f / v;
}

// ===========================================================================
// Projection GEMM (fp32 in, fp16 out): C = A[8192,512] @ B[512,512]
//   OMODE 0: C half [r][c] (ldc=DD)
//   OMODE 1: C half transposed per batch: vt[b][c][s]
// ===========================================================================
#define AW 20
#define BWNN 136

template <int OMODE>
__global__ void __launch_bounds__(256, 2)
gemm_proj(const float* __restrict__ A, const float* __restrict__ B,
          __half* __restrict__ C)
{
    __shared__ uint32_t As[128 * AW];
    __shared__ uint32_t Bs[16 * BWNN];

    const int tid  = threadIdx.x;
    const int lane = tid & 31;
    const int wid  = tid >> 5;
    const int warp_m = wid >> 2;
    const int warp_n = wid & 3;
    const int g   = lane >> 2;
    const int tig = lane & 3;
    const int row0 = blockIdx.y * 128;
    const int col0 = blockIdx.x * 128;

    int a_r[4], a_cf[4], a_cw[4];
#pragma unroll
    for (int i = 0; i < 4; i++) {
        int idx = tid + i * 256;
        a_r[i]  = idx >> 3;
        a_cf[i] = (idx & 7) * 4;
        a_cw[i] = (idx & 7) * 2;
    }
    int b_j[2], b_n4[2];
#pragma unroll
    for (int i = 0; i < 2; i++) {
        int idx = tid + i * 256;
        b_j[i]  = idx >> 5;
        b_n4[i] = (idx & 31) * 4;
    }

    float4 ra[4], rb[4];
    float acc[4][4][4];
#pragma unroll
    for (int mt = 0; mt < 4; mt++)
#pragma unroll
        for (int nt = 0; nt < 4; nt++)
#pragma unroll
            for (int i = 0; i < 4; i++) acc[mt][nt][i] = 0.0f;

    auto LOAD = [&](int k0) {
#pragma unroll
        for (int i = 0; i < 4; i++)
            ra[i] = *(const float4*)&A[(long long)(row0 + a_r[i]) * DD + k0 + a_cf[i]];
#pragma unroll
        for (int i = 0; i < 2; i++) {
            rb[2*i]   = *(const float4*)&B[(long long)(k0 + 2*b_j[i])     * DD + col0 + b_n4[i]];
            rb[2*i+1] = *(const float4*)&B[(long long)(k0 + 2*b_j[i] + 1) * DD + col0 + b_n4[i]];
        }
    };
    auto STORE = [&]() {
#pragma unroll
        for (int i = 0; i < 4; i++) {
            uint2 w;
            w.x = pack2(ra[i].x, ra[i].y);
            w.y = pack2(ra[i].z, ra[i].w);
            *(uint2*)&As[a_r[i] * AW + a_cw[i]] = w;
        }
#pragma unroll
        for (int i = 0; i < 2; i++) {
            uint4 w;
            w.x = pack2(rb[2*i].x, rb[2*i+1].x);
            w.y = pack2(rb[2*i].y, rb[2*i+1].y);
            w.z = pack2(rb[2*i].z, rb[2*i+1].z);
            w.w = pack2(rb[2*i].w, rb[2*i+1].w);
            *(uint4*)&Bs[b_j[i] * BWNN + b_n4[i]] = w;
        }
    };
    auto COMPUTE = [&]() {
#pragma unroll
        for (int s = 0; s < 2; s++) {
            const int c0 = s * 8;
            uint32_t af[4][4];
#pragma unroll
            for (int mt = 0; mt < 4; mt++) {
                const int m = warp_m * 64 + mt * 16;
                af[mt][0] = As[(m + g)     * AW + c0 + tig];
                af[mt][1] = As[(m + g + 8) * AW + c0 + tig];
                af[mt][2] = As[(m + g)     * AW + c0 + tig + 4];
                af[mt][3] = As[(m + g + 8) * AW + c0 + tig + 4];
            }
#pragma unroll
            for (int nt = 0; nt < 4; nt++) {
                const int nb = warp_n * 32 + nt * 8;
                uint32_t b0 = Bs[(c0 + tig)     * BWNN + nb + g];
                uint32_t b1 = Bs[(c0 + tig + 4) * BWNN + nb + g];
#pragma unroll
                for (int mt = 0; mt < 4; mt++) {
                    asm volatile(
                        "mma.sync.aligned.m16n8k16.row.col.f32.f16.f16.f32 "
                        "{%0,%1,%2,%3}, {%4,%5,%6,%7}, {%8,%9}, {%0,%1,%2,%3};"
                        : "+f"(acc[mt][nt][0]), "+f"(acc[mt][nt][1]),
                          "+f"(acc[mt][nt][2]), "+f"(acc[mt][nt][3])
                        : "r"(af[mt][0]), "r"(af[mt][1]),
                          "r"(af[mt][2]), "r"(af[mt][3]),
                          "r"(b0), "r"(b1));
                }
            }
        }
    };

    const int nT = DD / 32;
    LOAD(0);
    STORE();
    __syncthreads();
    for (int t = 1; t < nT; t++) {
        LOAD(t * 32);
        COMPUTE();
        __syncthreads();
        STORE();
        __syncthreads();
    }
    COMPUTE();

#pragma unroll
    for (int mt = 0; mt < 4; mt++) {
        const int r = row0 + warp_m * 64 + mt * 16 + g;
#pragma unroll
        for (int nt = 0; nt < 4; nt++) {
            const int c = col0 + warp_n * 32 + nt * 8 + tig * 2;
            if (OMODE == 0) {
                *(__half2*)&C[(long long)r * DD + c] =
                    __floats2half2_rn(acc[mt][nt][0], acc[mt][nt][1]);
                *(__half2*)&C[(long long)(r + 8) * DD + c] =
                    __floats2half2_rn(acc[mt][nt][2], acc[mt][nt][3]);
            } else {
                const int b  = r >> 12;
                const int sr = r & (SS - 1);
                __half* base = C + (long long)b * DD * SS;
                base[(long long)(c)     * SS + sr]     = __float2half_rn(acc[mt][nt][0]);
                base[(long long)(c + 1) * SS + sr]     = __float2half_rn(acc[mt][nt][1]);
                base[(long long)(c)     * SS + sr + 8] = __float2half_rn(acc[mt][nt][2]);
                base[(long long)(c + 1) * SS + sr + 8] = __float2half_rn(acc[mt][nt][3]);
            }
        }
    }
}

// ---------------------------------------------------------------------------
extern "C" void kernel_launch(void* const* d_in, const int* in_sizes, int n_in,
                              void* d_out, int out_size)
{
    const float* x  = (const float*)d_in[0];
    const float* wq = (const float*)d_in[1];
    const float* wk = (const float*)d_in[2];
    const float* wv = (const float*)d_in[3];
    float* out = (float*)d_out;

    __half *qh, *kh, *vt, *p;
    float *part, *rsum;
    cudaGetSymbolAddress((void**)&qh,   g_qh);
    cudaGetSymbolAddress((void**)&kh,   g_kh);
    cudaGetSymbolAddress((void**)&vt,   g_vt);
    cudaGetSymbolAddress((void**)&p,    g_p);
    cudaGetSymbolAddress((void**)&part, g_part);
    cudaGetSymbolAddress((void**)&rsum, g_rsum);

    const long long qkvStride = (long long)SS * DD;
    const long long sStride   = (long long)SS * SS;
    const float scale = 1.0f / sqrtf((float)DD);
    const int smemBytes = 4 * 16384;

    cudaFuncSetAttribute(gemm_h_nt<0>,
                         cudaFuncAttributeMaxDynamicSharedMemorySize, smemBytes);
    cudaFuncSetAttribute(gemm_h_nt<1>,
                         cudaFuncAttributeMaxDynamicSharedMemorySize, smemBytes);

    // 1) QKV projections (fp32 in, fp16 out; V transposed)
    {
        dim3 grid(DD / 128, (BB * SS) / 128, 1), blk(256);
        gemm_proj<0><<<grid, blk>>>(x, wq, qh);
        gemm_proj<0><<<grid, blk>>>(x, wk, kh);
        gemm_proj<1><<<grid, blk>>>(x, wv, vt);
    }

    // 2) P = exp(scale * Q @ K^T) fp16 + partial row sums, per batch
    {
        dim3 grid(SS / 128, SS / 128, BB), blk(128);
        gemm_h_nt<0><<<grid, blk, smemBytes>>>(qh, kh, nullptr, p, part, nullptr,
                                               DD, DD, DD, SS,
                                               qkvStride, qkvStride, sStride, scale);
    }

    // 3) rsum_inv[row] = 1 / sum of 64 partials
    {
        rowsum_inv<<<(BB * SS) / 8, 256>>>(part, rsum);
    }

    // 4) context = (P @ Vt^T) * rsum_inv, per batch
    {
        dim3 grid(DD / 128, SS / 128, BB), blk(128);
        gemm_h_nt<1><<<grid, blk, smemBytes>>>(p, vt, out, nullptr, nullptr, rsum,
                                               SS, SS, SS, DD,
                                               sStride, qkvStride, qkvStride, 1.0f);
    }
}

// round 15
// speedup vs baseline: 1.1757x; 1.1757x over previous
#include <cuda_runtime.h>
#include <cuda_fp16.h>
#include <math.h>
#include <stdint.h>

// Problem dims (fixed)
#define BB 2
#define SS 4096
#define DD 512

// Scratch (device globals: allocation-free rule)
__device__ __align__(256) __half g_qh[(size_t)BB * SS * DD];   // Q [b][s][d] fp16
__device__ __align__(256) __half g_kh[(size_t)BB * SS * DD];   // K [b][s][d] fp16
__device__ __align__(256) __half g_vt[(size_t)BB * DD * SS];   // V^T [b][d][s] fp16
__device__ __align__(256) __half g_p [(size_t)BB * SS * SS];   // unnormalized exp(S) fp16
__device__ __align__(256) float  g_part[(size_t)BB * SS * 64]; // partial row sums
__device__ __align__(256) float  g_rsum[(size_t)BB * SS];      // 1 / rowsum
__device__ __align__(256) float  g_ctx[(size_t)2 * BB * SS * DD]; // PV split-K partials

__device__ __forceinline__ uint32_t pack2(float lo, float hi) {
    __half2 h = __floats2half2_rn(lo, hi);
    return *(uint32_t*)&h;
}
__device__ __forceinline__ uint32_t smem_u32(const void* p) {
    uint32_t a;
    asm("{ .reg .u64 t; cvta.to.shared.u64 t, %1; cvt.u32.u64 %0, t; }"
        : "=r"(a) : "l"(p));
    return a;
}

#define CPA16(dst, src) \
    asm volatile("cp.async.cg.shared.global [%0], [%1], 16;" \
                 :: "r"(dst), "l"(src) : "memory")
#define CPA_COMMIT() asm volatile("cp.async.commit_group;" ::: "memory")
#define CPA_WAIT2()  asm volatile("cp.async.wait_group 2;" ::: "memory")

// ===========================================================================
// NT fp16-operand GEMM, 4-stage cp.async pipeline (round-13 proven core:
// __launch_bounds__(128,2), bf fragment buffer, 218 regs).
// MODE 0 (QK): z = batch. Epilogue e = expf(scale*acc) -> fp16 P + partial
//              row sums.
// MODE 1 (PV split-K): z = batch*2 + khalf; A,B offset by khalf*2048 in K;
//              epilogue stores raw fp32 partial to Cf[z-slab].
// ===========================================================================
template <int MODE>
__global__ void __launch_bounds__(128, 2)
gemm_h_nt(const __half* __restrict__ A, const __half* __restrict__ B,
          float* __restrict__ Cf, __half* __restrict__ Ch,
          float* __restrict__ part,
          int K, int lda, int ldb, int ldc,
          long long sA, long long sB, float alpha)
{
    extern __shared__ uint32_t sm[];            // 4 stages * 4096 words
    const uint32_t smb = smem_u32(sm);

    long long zrow;
    if (MODE == 0) {
        A += (long long)blockIdx.z * sA;
        B += (long long)blockIdx.z * sB;
        zrow = (long long)blockIdx.z * SS;
    } else {
        const int batch = blockIdx.z >> 1;
        const int kh    = blockIdx.z & 1;
        A += (long long)batch * sA + (long long)kh * 2048;
        B += (long long)batch * sB + (long long)kh * 2048;
        Cf += (long long)blockIdx.z * ((long long)SS * DD);
        zrow = 0;
    }

    const int tid  = threadIdx.x;
    const int lane = tid & 31;
    const int wid  = tid >> 5;
    const int warp_m = wid >> 1;
    const int warp_n = wid & 1;
    const int g   = lane >> 2;
    const int tig = lane & 3;

    const int row0 = blockIdx.y * 128;
    const int col0 = blockIdx.x * 128;

    uint32_t stA[4], stB[4];
    const char* pA[4];
    const char* pB[4];
#pragma unroll
    for (int i = 0; i < 4; i++) {
        int idx = tid + i * 128;
        int r = idx >> 2, c = idx & 3;
        uint32_t off = (uint32_t)(r * 16 + ((c ^ ((r >> 1) & 3)) << 2)) * 4u;
        stA[i] = smb + off;
        stB[i] = smb + 8192 + off;
        pA[i] = (const char*)(A + (long long)(row0 + r) * lda + c * 8);
        pB[i] = (const char*)(B + (long long)(col0 + r) * ldb + c * 8);
    }

    const int lc = (g >> 1) & 3;
    int fa[4], fb[4];
#pragma unroll
    for (int c = 0; c < 4; c++) {
        fa[c] = (warp_m * 64 + g) * 16 + ((c ^ lc) << 2) + tig;
        fb[c] = 2048 + (warp_n * 64 + g) * 16 + ((c ^ lc) << 2) + tig;
    }

    float acc[4][8][4];
#pragma unroll
    for (int mt = 0; mt < 4; mt++)
#pragma unroll
        for (int nt = 0; nt < 8; nt++)
#pragma unroll
            for (int i = 0; i < 4; i++) acc[mt][nt][i] = 0.0f;

    auto FILL = [&](int t, int st) {
        const long long kb = (long long)t * 64;
        const uint32_t so = (uint32_t)st * 16384u;
#pragma unroll
        for (int i = 0; i < 4; i++) CPA16(stA[i] + so, pA[i] + kb);
#pragma unroll
        for (int i = 0; i < 4; i++) CPA16(stB[i] + so, pB[i] + kb);
    };

    auto COMPUTE = [&](int st) {
        const uint32_t* Sb = sm + st * 4096;
#pragma unroll
        for (int s = 0; s < 2; s++) {
            uint32_t af[4][4], bf[8][2];
#pragma unroll
            for (int mt = 0; mt < 4; mt++) {
                af[mt][0] = Sb[fa[2*s]     + mt * 256];
                af[mt][1] = Sb[fa[2*s]     + mt * 256 + 128];
                af[mt][2] = Sb[fa[2*s + 1] + mt * 256];
                af[mt][3] = Sb[fa[2*s + 1] + mt * 256 + 128];
            }
#pragma unroll
            for (int nt = 0; nt < 8; nt++) {
                bf[nt][0] = Sb[fb[2*s]     + nt * 128];
                bf[nt][1] = Sb[fb[2*s + 1] + nt * 128];
            }
#pragma unroll
            for (int nt = 0; nt < 8; nt++)
#pragma unroll
                for (int mt = 0; mt < 4; mt++) {
                    asm volatile(
                        "mma.sync.aligned.m16n8k16.row.col.f32.f16.f16.f32 "
                        "{%0,%1,%2,%3}, {%4,%5,%6,%7}, {%8,%9}, {%0,%1,%2,%3};"
                        : "+f"(acc[mt][nt][0]), "+f"(acc[mt][nt][1]),
                          "+f"(acc[mt][nt][2]), "+f"(acc[mt][nt][3])
                        : "r"(af[mt][0]), "r"(af[mt][1]),
                          "r"(af[mt][2]), "r"(af[mt][3]),
                          "r"(bf[nt][0]), "r"(bf[nt][1]));
                }
        }
    };

    const int nT = K / 32;                // divisible by 4 for our shapes
    FILL(0, 0); CPA_COMMIT();
    FILL(1, 1); CPA_COMMIT();
    FILL(2, 2); CPA_COMMIT();

    for (int t0 = 0; t0 < nT; t0 += 4) {
#pragma unroll
        for (int u = 0; u < 4; u++) {
            const int t = t0 + u;
            CPA_WAIT2();
            __syncthreads();
            if (t + 3 < nT) FILL(t + 3, (u + 3) & 3);
            CPA_COMMIT();
            COMPUTE(u);
        }
    }

    if (MODE == 0) {
        // exp epilogue: P (fp16, unnormalized) + deterministic partial sums
        Ch += zrow * SS;
#pragma unroll
        for (int mt = 0; mt < 4; mt++) {
            const int r = row0 + warp_m * 64 + mt * 16 + g;
            float s0 = 0.0f, s1 = 0.0f;
#pragma unroll
            for (int nt = 0; nt < 8; nt++) {
                const int c = col0 + warp_n * 64 + nt * 8 + tig * 2;
                float e0 = __expf(acc[mt][nt][0] * alpha);
                float e1 = __expf(acc[mt][nt][1] * alpha);
                float e2 = __expf(acc[mt][nt][2] * alpha);
                float e3 = __expf(acc[mt][nt][3] * alpha);
                s0 += e0 + e1;
                s1 += e2 + e3;
                *(__half2*)&Ch[(long long)r * ldc + c]       = __floats2half2_rn(e0, e1);
                *(__half2*)&Ch[(long long)(r + 8) * ldc + c] = __floats2half2_rn(e2, e3);
            }
            s0 += __shfl_xor_sync(0xFFFFFFFF, s0, 1);
            s0 += __shfl_xor_sync(0xFFFFFFFF, s0, 2);
            s1 += __shfl_xor_sync(0xFFFFFFFF, s1, 1);
            s1 += __shfl_xor_sync(0xFFFFFFFF, s1, 2);
            if (tig == 0) {
                const int slot = blockIdx.x * 2 + warp_n;
                part[(zrow + r)     * 64 + slot] = s0;
                part[(zrow + r + 8) * 64 + slot] = s1;
            }
        }
    } else {
        // raw fp32 partial slab
#pragma unroll
        for (int mt = 0; mt < 4; mt++) {
            const int r = row0 + warp_m * 64 + mt * 16 + g;
#pragma unroll
            for (int nt = 0; nt < 8; nt++) {
                const int c = col0 + warp_n * 64 + nt * 8 + tig * 2;
                float2 v0, v1;
                v0.x = acc[mt][nt][0]; v0.y = acc[mt][nt][1];
                v1.x = acc[mt][nt][2]; v1.y = acc[mt][nt][3];
                *(float2*)&Cf[(long long)r * ldc + c]       = v0;
                *(float2*)&Cf[(long long)(r + 8) * ldc + c] = v1;
            }
        }
    }
}

// ---------------------------------------------------------------------------
// rowsum reduce: rsum_inv[row] = 1 / sum(part[row][0..63]).
// ---------------------------------------------------------------------------
__global__ void __launch_bounds__(256)
rowsum_inv(const float* __restrict__ part, float* __restrict__ rsum)
{
    const int row  = blockIdx.x * 8 + (threadIdx.x >> 5);
    const int lane = threadIdx.x & 31;
    const float* p = part + (long long)row * 64;
    float v = p[lane] + p[lane + 32];
#pragma unroll
    for (int o = 16; o > 0; o >>= 1)
        v += __shfl_xor_sync(0xFFFFFFFF, v, o);
    if (lane == 0) rsum[row] = 1.0f / v;
}

// ---------------------------------------------------------------------------
// Split-K combine: out[e] = (part[e + b*slab] + part[e + b*slab + slab]) *
//                  rsum_inv[e / DD],  slab = SS*DD, partial layout [b][kh].
// One float4 per thread.
// ---------------------------------------------------------------------------
__global__ void __launch_bounds__(256)
combine_ctx(const float* __restrict__ ctx, const float* __restrict__ rsum,
            float* __restrict__ out)
{
    const long long e4 = (long long)blockIdx.x * 256 + threadIdx.x;  // float4 idx
    const long long e  = e4 * 4;
    const long long slab = (long long)SS * DD;
    const int b = (int)(e / slab);
    const float inv = rsum[e / DD];
    float4 p0 = *(const float4*)&ctx[e + (long long)b * slab];
    float4 p1 = *(const float4*)&ctx[e + (long long)b * slab + slab];
    float4 o;
    o.x = (p0.x + p1.x) * inv;
    o.y = (p0.y + p1.y) * inv;
    o.z = (p0.z + p1.z) * inv;
    o.w = (p0.w + p1.w) * inv;
    *(float4*)&out[e] = o;
}

// ===========================================================================
// Projection GEMM (fp32 in, fp16 out): C = A[8192,512] @ B[512,512]
//   OMODE 0: C half [r][c] (ldc=DD)
//   OMODE 1: C half transposed per batch: vt[b][c][s]
// ===========================================================================
#define AW 20
#define BWNN 136

template <int OMODE>
__global__ void __launch_bounds__(256, 2)
gemm_proj(const float* __restrict__ A, const float* __restrict__ B,
          __half* __restrict__ C)
{
    __shared__ uint32_t As[128 * AW];
    __shared__ uint32_t Bs[16 * BWNN];

    const int tid  = threadIdx.x;
    const int lane = tid & 31;
    const int wid  = tid >> 5;
    const int warp_m = wid >> 2;
    const int warp_n = wid & 3;
    const int g   = lane >> 2;
    const int tig = lane & 3;
    const int row0 = blockIdx.y * 128;
    const int col0 = blockIdx.x * 128;

    int a_r[4], a_cf[4], a_cw[4];
#pragma unroll
    for (int i = 0; i < 4; i++) {
        int idx = tid + i * 256;
        a_r[i]  = idx >> 3;
        a_cf[i] = (idx & 7) * 4;
        a_cw[i] = (idx & 7) * 2;
    }
    int b_j[2], b_n4[2];
#pragma unroll
    for (int i = 0; i < 2; i++) {
        int idx = tid + i * 256;
        b_j[i]  = idx >> 5;
        b_n4[i] = (idx & 31) * 4;
    }

    float4 ra[4], rb[4];
    float acc[4][4][4];
#pragma unroll
    for (int mt = 0; mt < 4; mt++)
#pragma unroll
        for (int nt = 0; nt < 4; nt++)
#pragma unroll
            for (int i = 0; i < 4; i++) acc[mt][nt][i] = 0.0f;

    auto LOAD = [&](int k0) {
#pragma unroll
        for (int i = 0; i < 4; i++)
            ra[i] = *(const float4*)&A[(long long)(row0 + a_r[i]) * DD + k0 + a_cf[i]];
#pragma unroll
        for (int i = 0; i < 2; i++) {
            rb[2*i]   = *(const float4*)&B[(long long)(k0 + 2*b_j[i])     * DD + col0 + b_n4[i]];
            rb[2*i+1] = *(const float4*)&B[(long long)(k0 + 2*b_j[i] + 1) * DD + col0 + b_n4[i]];
        }
    };
    auto STORE = [&]() {
#pragma unroll
        for (int i = 0; i < 4; i++) {
            uint2 w;
            w.x = pack2(ra[i].x, ra[i].y);
            w.y = pack2(ra[i].z, ra[i].w);
            *(uint2*)&As[a_r[i] * AW + a_cw[i]] = w;
        }
#pragma unroll
        for (int i = 0; i < 2; i++) {
            uint4 w;
            w.x = pack2(rb[2*i].x, rb[2*i+1].x);
            w.y = pack2(rb[2*i].y, rb[2*i+1].y);
            w.z = pack2(rb[2*i].z, rb[2*i+1].z);
            w.w = pack2(rb[2*i].w, rb[2*i+1].w);
            *(uint4*)&Bs[b_j[i] * BWNN + b_n4[i]] = w;
        }
    };
    auto COMPUTE = [&]() {
#pragma unroll
        for (int s = 0; s < 2; s++) {
            const int c0 = s * 8;
            uint32_t af[4][4];
#pragma unroll
            for (int mt = 0; mt < 4; mt++) {
                const int m = warp_m * 64 + mt * 16;
                af[mt][0] = As[(m + g)     * AW + c0 + tig];
                af[mt][1] = As[(m + g + 8) * AW + c0 + tig];
                af[mt][2] = As[(m + g)     * AW + c0 + tig + 4];
                af[mt][3] = As[(m + g + 8) * AW + c0 + tig + 4];
            }
#pragma unroll
            for (int nt = 0; nt < 4; nt++) {
                const int nb = warp_n * 32 + nt * 8;
                uint32_t b0 = Bs[(c0 + tig)     * BWNN + nb + g];
                uint32_t b1 = Bs[(c0 + tig + 4) * BWNN + nb + g];
#pragma unroll
                for (int mt = 0; mt < 4; mt++) {
                    asm volatile(
                        "mma.sync.aligned.m16n8k16.row.col.f32.f16.f16.f32 "
                        "{%0,%1,%2,%3}, {%4,%5,%6,%7}, {%8,%9}, {%0,%1,%2,%3};"
                        : "+f"(acc[mt][nt][0]), "+f"(acc[mt][nt][1]),
                          "+f"(acc[mt][nt][2]), "+f"(acc[mt][nt][3])
                        : "r"(af[mt][0]), "r"(af[mt][1]),
                          "r"(af[mt][2]), "r"(af[mt][3]),
                          "r"(b0), "r"(b1));
                }
            }
        }
    };

    const int nT = DD / 32;
    LOAD(0);
    STORE();
    __syncthreads();
    for (int t = 1; t < nT; t++) {
        LOAD(t * 32);
        COMPUTE();
        __syncthreads();
        STORE();
        __syncthreads();
    }
    COMPUTE();

#pragma unroll
    for (int mt = 0; mt < 4; mt++) {
        const int r = row0 + warp_m * 64 + mt * 16 + g;
#pragma unroll
        for (int nt = 0; nt < 4; nt++) {
            const int c = col0 + warp_n * 32 + nt * 8 + tig * 2;
            if (OMODE == 0) {
                *(__half2*)&C[(long long)r * DD + c] =
                    __floats2half2_rn(acc[mt][nt][0], acc[mt][nt][1]);
                *(__half2*)&C[(long long)(r + 8) * DD + c] =
                    __floats2half2_rn(acc[mt][nt][2], acc[mt][nt][3]);
            } else {
                const int b  = r >> 12;
                const int sr = r & (SS - 1);
                __half* base = C + (long long)b * DD * SS;
                base[(long long)(c)     * SS + sr]     = __float2half_rn(acc[mt][nt][0]);
                base[(long long)(c + 1) * SS + sr]     = __float2half_rn(acc[mt][nt][1]);
                base[(long long)(c)     * SS + sr + 8] = __float2half_rn(acc[mt][nt][2]);
                base[(long long)(c + 1) * SS + sr + 8] = __float2half_rn(acc[mt][nt][3]);
            }
        }
    }
}

// ---------------------------------------------------------------------------
extern "C" void kernel_launch(void* const* d_in, const int* in_sizes, int n_in,
                              void* d_out, int out_size)
{
    const float* x  = (const float*)d_in[0];
    const float* wq = (const float*)d_in[1];
    const float* wk = (const float*)d_in[2];
    const float* wv = (const float*)d_in[3];
    float* out = (float*)d_out;

    __half *qh, *kh, *vt, *p;
    float *part, *rsum, *ctx;
    cudaGetSymbolAddress((void**)&qh,   g_qh);
    cudaGetSymbolAddress((void**)&kh,   g_kh);
    cudaGetSymbolAddress((void**)&vt,   g_vt);
    cudaGetSymbolAddress((void**)&p,    g_p);
    cudaGetSymbolAddress((void**)&part, g_part);
    cudaGetSymbolAddress((void**)&rsum, g_rsum);
    cudaGetSymbolAddress((void**)&ctx,  g_ctx);

    const long long qkvStride = (long long)SS * DD;
    const long long sStride   = (long long)SS * SS;
    const float scale = 1.0f / sqrtf((float)DD);
    const int smemBytes = 4 * 16384;

    cudaFuncSetAttribute(gemm_h_nt<0>,
                         cudaFuncAttributeMaxDynamicSharedMemorySize, smemBytes);
    cudaFuncSetAttribute(gemm_h_nt<1>,
                         cudaFuncAttributeMaxDynamicSharedMemorySize, smemBytes);

    // 1) QKV projections (fp32 in, fp16 out; V transposed)
    {
        dim3 grid(DD / 128, (BB * SS) / 128, 1), blk(256);
        gemm_proj<0><<<grid, blk>>>(x, wq, qh);
        gemm_proj<0><<<grid, blk>>>(x, wk, kh);
        gemm_proj<1><<<grid, blk>>>(x, wv, vt);
    }

    // 2) P = exp(scale * Q @ K^T) fp16 + partial row sums, per batch
    {
        dim3 grid(SS / 128, SS / 128, BB), blk(128);
        gemm_h_nt<0><<<grid, blk, smemBytes>>>(qh, kh, nullptr, p, part,
                                               DD, DD, DD, SS,
                                               qkvStride, qkvStride, scale);
    }

    // 3) rsum_inv[row] = 1 / sum of 64 partials
    {
        rowsum_inv<<<(BB * SS) / 8, 256>>>(part, rsum);
    }

    // 4) PV split-K=2: 512 CTAs -> balanced occupancy; fp32 partial slabs
    {
        dim3 grid(DD / 128, SS / 128, BB * 2), blk(128);
        gemm_h_nt<1><<<grid, blk, smemBytes>>>(p, vt, ctx, nullptr, nullptr,
                                               2048, SS, SS, DD,
                                               sStride, qkvStride, 1.0f);
    }

    // 5) combine partials + normalize
    {
        const long long n4 = (long long)BB * SS * DD / 4;
        combine_ctx<<<(unsigned)(n4 / 256), 256>>>(ctx, rsum, out);
    }
}